// round 1
// baseline (speedup 1.0000x reference)
#include <cuda_runtime.h>
#include <math.h>

#define N_BATCH 4
#define C_DIM   256
#define P_DIM   4096        // 64*64
#define HB      0.5f
#define EPS     1e-5f

// ---------------- scratch (static device globals; no allocation) ------------
__device__ float g_mu[C_DIM];
__device__ float g_xn[(size_t)N_BATCH * C_DIM * P_DIM];           // 16 MB, layout [n][c][p]
__device__ float g_yn[(size_t)N_BATCH * C_DIM * P_DIM];           // 16 MB
__device__ float g_cos[(size_t)N_BATCH * P_DIM * P_DIM];          // 256 MB, layout [n][p][q]
__device__ float g_rowm[N_BATCH * P_DIM];
__device__ float g_rowb[N_BATCH * P_DIM];
__device__ float g_rowrl[N_BATCH * P_DIM];
#define P_CHUNKS 8
__device__ float g_colM[N_BATCH * P_CHUNKS * P_DIM];              // partial column maxes
__device__ float g_cxpart[N_BATCH * 16];                          // partial sums per n

// ---------------- K1: per-channel mean of y over (n, p) ---------------------
__global__ void k_mean(const float* __restrict__ y) {
    int c = blockIdx.x;
    int tid = threadIdx.x;
    float s = 0.f;
    for (int n = 0; n < N_BATCH; n++) {
        const float* base = y + ((size_t)n * C_DIM + c) * P_DIM;
        for (int p = tid; p < P_DIM; p += 256) s += base[p];
    }
    __shared__ float sm[256];
    sm[tid] = s; __syncthreads();
    for (int o = 128; o > 0; o >>= 1) {
        if (tid < o) sm[tid] += sm[tid + o];
        __syncthreads();
    }
    if (tid == 0) g_mu[c] = sm[0] * (1.f / (float)(N_BATCH * P_DIM));
}

// ---------------- K2: center + L2-normalize over channels -------------------
// One thread per (n, p). Threads in a warp have consecutive p -> every global
// access (stride C over the c loop) is a fully coalesced 128B segment.
__global__ __launch_bounds__(256) void k_norm(const float* __restrict__ x,
                                              const float* __restrict__ y) {
    __shared__ float mu[C_DIM];
    int tid = threadIdx.x;
    if (tid < C_DIM) mu[tid] = g_mu[tid];
    __syncthreads();

    int idx = blockIdx.x * 256 + tid;          // 0 .. N*P-1
    int n = idx / P_DIM, p = idx % P_DIM;
    const float* xb = x + (size_t)n * C_DIM * P_DIM + p;
    const float* yb = y + (size_t)n * C_DIM * P_DIM + p;

    float sx = 0.f, sy = 0.f;
    #pragma unroll 8
    for (int c = 0; c < C_DIM; c++) {
        float m  = mu[c];
        float xv = xb[(size_t)c * P_DIM] - m;
        float yv = yb[(size_t)c * P_DIM] - m;
        sx += xv * xv;
        sy += yv * yv;
    }
    float rx = rsqrtf(sx), ry = rsqrtf(sy);

    float* xo = g_xn + (size_t)n * C_DIM * P_DIM + p;
    float* yo = g_yn + (size_t)n * C_DIM * P_DIM + p;
    #pragma unroll 8
    for (int c = 0; c < C_DIM; c++) {
        float m = mu[c];
        xo[(size_t)c * P_DIM] = (xb[(size_t)c * P_DIM] - m) * rx;
        yo[(size_t)c * P_DIM] = (yb[(size_t)c * P_DIM] - m) * ry;
    }
}

// ---------------- K3: per-batch SGEMM  cos = A^T B  --------------------------
// A = xn[n] (C x P), B = yn[n] (C x P), both K-major -> classic TN tiling.
#define BM 64
#define BN 64
#define BK 16
__global__ __launch_bounds__(256) void k_gemm() {
    int n  = blockIdx.z;
    const float* A = g_xn + (size_t)n * C_DIM * P_DIM;
    const float* B = g_yn + (size_t)n * C_DIM * P_DIM;
    float* Cm      = g_cos + (size_t)n * P_DIM * P_DIM;

    __shared__ float As[BK][BM];
    __shared__ float Bs[BK][BN];

    int tid = threadIdx.x;
    int tx = tid % 16, ty = tid / 16;
    int m0 = blockIdx.x * BM, n0 = blockIdx.y * BN;

    int lr = tid / 16;          // k-row within tile (0..15)
    int lc = (tid % 16) * 4;    // column quad within tile

    float acc[4][4] = {};

    for (int k0 = 0; k0 < C_DIM; k0 += BK) {
        *(float4*)&As[lr][lc] = *(const float4*)&A[(size_t)(k0 + lr) * P_DIM + m0 + lc];
        *(float4*)&Bs[lr][lc] = *(const float4*)&B[(size_t)(k0 + lr) * P_DIM + n0 + lc];
        __syncthreads();
        #pragma unroll
        for (int kk = 0; kk < BK; kk++) {
            float4 a4 = *(float4*)&As[kk][ty * 4];
            float4 b4 = *(float4*)&Bs[kk][tx * 4];
            float ar[4] = {a4.x, a4.y, a4.z, a4.w};
            float br[4] = {b4.x, b4.y, b4.z, b4.w};
            #pragma unroll
            for (int i = 0; i < 4; i++)
                #pragma unroll
                for (int j = 0; j < 4; j++)
                    acc[i][j] += ar[i] * br[j];
        }
        __syncthreads();
    }

    #pragma unroll
    for (int i = 0; i < 4; i++) {
        float4 v = make_float4(acc[i][0], acc[i][1], acc[i][2], acc[i][3]);
        *(float4*)&Cm[(size_t)(m0 + ty * 4 + i) * P_DIM + n0 + tx * 4] = v;
    }
}

// ---------------- K4: per-row max, beta, 1/sum(exp) --------------------------
__global__ __launch_bounds__(256) void k_row() {
    int n = blockIdx.y;
    int p = blockIdx.x;
    const float* row = g_cos + ((size_t)n * P_DIM + p) * P_DIM;
    int tid = threadIdx.x;

    __shared__ float sr[P_DIM];   // 16 KB row cache
    __shared__ float red[256];

    float m = -1e30f;
    for (int q = tid; q < P_DIM; q += 256) {
        float v = row[q];
        sr[q] = v;
        m = fmaxf(m, v);
    }
    red[tid] = m; __syncthreads();
    for (int o = 128; o > 0; o >>= 1) {
        if (tid < o) red[tid] = fmaxf(red[tid], red[tid + o]);
        __syncthreads();
    }
    m = red[0];
    __syncthreads();

    float dmin = 1.f - m;
    float beta = 1.f / (HB * (dmin + EPS));

    float s = 0.f;
    for (int q = tid; q < P_DIM; q += 256)
        s += expf(beta * (sr[q] - m));
    red[tid] = s; __syncthreads();
    for (int o = 128; o > 0; o >>= 1) {
        if (tid < o) red[tid] += red[tid + o];
        __syncthreads();
    }
    if (tid == 0) {
        g_rowm[n * P_DIM + p]  = m;
        g_rowb[n * P_DIM + p]  = beta;
        g_rowrl[n * P_DIM + p] = 1.f / red[0];
    }
}

// ---------------- K5a: partial column max over p chunks ----------------------
// grid: (P/256, P_CHUNKS, N). Thread owns one q; iterates a 512-row p-chunk.
__global__ __launch_bounds__(256) void k_colA() {
    int n  = blockIdx.z;
    int pc = blockIdx.y;
    int q  = blockIdx.x * 256 + threadIdx.x;
    const int PC = P_DIM / P_CHUNKS;   // 512
    int p0 = pc * PC;

    const float* cm = g_cos + (size_t)n * P_DIM * P_DIM + q;
    const float* rm = g_rowm  + n * P_DIM;
    const float* rb = g_rowb  + n * P_DIM;
    const float* rl = g_rowrl + n * P_DIM;

    float M = 0.f;   // cx_ij values are > 0, so 0 is a safe identity
    #pragma unroll 4
    for (int p = p0; p < p0 + PC; p++) {
        float c = cm[(size_t)p * P_DIM];
        float v = expf(rb[p] * (c - rm[p])) * rl[p];
        M = fmaxf(M, v);
    }
    g_colM[(n * P_CHUNKS + pc) * P_DIM + q] = M;
}

// ---------------- K5b: finish column max, sum over q -------------------------
__global__ __launch_bounds__(256) void k_colB() {
    int n = blockIdx.y;
    int q = blockIdx.x * 256 + threadIdx.x;
    float M = 0.f;
    #pragma unroll
    for (int pc = 0; pc < P_CHUNKS; pc++)
        M = fmaxf(M, g_colM[(n * P_CHUNKS + pc) * P_DIM + q]);

    __shared__ float red[256];
    red[threadIdx.x] = M; __syncthreads();
    for (int o = 128; o > 0; o >>= 1) {
        if (threadIdx.x < o) red[threadIdx.x] += red[threadIdx.x + o];
        __syncthreads();
    }
    if (threadIdx.x == 0)
        g_cxpart[n * 16 + blockIdx.x] = red[0];
}

// ---------------- K6: final scalar loss --------------------------------------
__global__ void k_final(float* __restrict__ out) {
    if (threadIdx.x == 0) {
        float loss = 0.f;
        for (int n = 0; n < N_BATCH; n++) {
            float s = 0.f;
            for (int b = 0; b < 16; b++) s += g_cxpart[n * 16 + b];
            float cx = s * (1.f / (float)P_DIM);
            loss += -logf(cx + EPS);
        }
        out[0] = loss * (1.f / (float)N_BATCH);
    }
}

// ---------------- launch ------------------------------------------------------
extern "C" void kernel_launch(void* const* d_in, const int* in_sizes, int n_in,
                              void* d_out, int out_size) {
    const float* x = (const float*)d_in[0];
    const float* y = (const float*)d_in[1];
    float* out = (float*)d_out;

    k_mean<<<C_DIM, 256>>>(y);
    k_norm<<<(N_BATCH * P_DIM) / 256, 256>>>(x, y);

    dim3 gg(P_DIM / BM, P_DIM / BN, N_BATCH);
    k_gemm<<<gg, 256>>>();

    dim3 gr(P_DIM, N_BATCH);
    k_row<<<gr, 256>>>();

    dim3 gca(P_DIM / 256, P_CHUNKS, N_BATCH);
    k_colA<<<gca, 256>>>();

    dim3 gcb(P_DIM / 256, 1, N_BATCH);
    gcb.y = N_BATCH; gcb.z = 1;            // (16, 4)
    k_colB<<<gcb, 256>>>();

    k_final<<<1, 32>>>(out);
}

// round 2
// speedup vs baseline: 1.8471x; 1.8471x over previous
#include <cuda_runtime.h>
#include <math.h>
#include <stdint.h>

#define N_BATCH 4
#define C_DIM   256
#define P_DIM   4096        // 64*64
#define HB      0.5f
#define EPS     1e-5f
#define LOG2E   1.4426950408889634f

// ---------------- scratch (static device globals; no allocation) ------------
__device__ float g_mu[C_DIM];
__device__ float g_xn[(size_t)N_BATCH * C_DIM * P_DIM];           // 16 MB, [n][c][p], tf32-rounded
__device__ float g_yn[(size_t)N_BATCH * C_DIM * P_DIM];           // 16 MB
__device__ float g_cos[(size_t)N_BATCH * P_DIM * P_DIM];          // 256 MB, [n][p][q]
__device__ float g_b2[N_BATCH * P_DIM];                           // beta * log2(e)
__device__ float g_bias[N_BATCH * P_DIM];                         // -b2*m - log2(sum)
#define P_CHUNKS 8
__device__ float g_colM[N_BATCH * P_CHUNKS * P_DIM];              // partial column maxes
__device__ float g_cxpart[N_BATCH * 16];                          // partial sums per n

__device__ __forceinline__ float tf32r(float x) {
    asm("cvt.rna.tf32.f32 %0, %1;" : "=f"(x) : "f"(x));
    return x;
}

// ---------------- K1: per-channel mean of y over (n, p) ---------------------
__global__ void k_mean(const float* __restrict__ y) {
    int c = blockIdx.x;
    int tid = threadIdx.x;
    float s = 0.f;
    for (int n = 0; n < N_BATCH; n++) {
        const float* base = y + ((size_t)n * C_DIM + c) * P_DIM;
        for (int p = tid; p < P_DIM; p += 256) s += base[p];
    }
    __shared__ float sm[256];
    sm[tid] = s; __syncthreads();
    for (int o = 128; o > 0; o >>= 1) {
        if (tid < o) sm[tid] += sm[tid + o];
        __syncthreads();
    }
    if (tid == 0) g_mu[c] = sm[0] * (1.f / (float)(N_BATCH * P_DIM));
}

// ---------------- K2: center + L2-normalize over channels, tf32 round -------
__global__ __launch_bounds__(256) void k_norm(const float* __restrict__ x,
                                              const float* __restrict__ y) {
    __shared__ float mu[C_DIM];
    int tid = threadIdx.x;
    if (tid < C_DIM) mu[tid] = g_mu[tid];
    __syncthreads();

    int idx = blockIdx.x * 256 + tid;          // 0 .. N*P-1
    int n = idx / P_DIM, p = idx % P_DIM;
    const float* xb = x + (size_t)n * C_DIM * P_DIM + p;
    const float* yb = y + (size_t)n * C_DIM * P_DIM + p;

    float sx = 0.f, sy = 0.f;
    #pragma unroll 8
    for (int c = 0; c < C_DIM; c++) {
        float m  = mu[c];
        float xv = xb[(size_t)c * P_DIM] - m;
        float yv = yb[(size_t)c * P_DIM] - m;
        sx += xv * xv;
        sy += yv * yv;
    }
    float rx = rsqrtf(sx), ry = rsqrtf(sy);

    float* xo = g_xn + (size_t)n * C_DIM * P_DIM + p;
    float* yo = g_yn + (size_t)n * C_DIM * P_DIM + p;
    #pragma unroll 8
    for (int c = 0; c < C_DIM; c++) {
        float m = mu[c];
        xo[(size_t)c * P_DIM] = tf32r((xb[(size_t)c * P_DIM] - m) * rx);
        yo[(size_t)c * P_DIM] = tf32r((yb[(size_t)c * P_DIM] - m) * ry);
    }
}

// ---------------- K3: tf32 tensor-core SGEMM  cos = A^T B --------------------
// A = xn[n] (K x M, K-major), B = yn[n] (K x N). Block tile 128x128, BK=16.
// 8 warps: 4 (m) x 2 (n), warp tile 32x64 via mma.m16n8k8.
#define GBM 128
#define GBN 128
#define GBK 16
#define SST 136     // smem row stride (floats): bank = (8k+g)%32, conflict-free

__device__ __forceinline__ void mma_tf32(float* c, const uint32_t* a, const uint32_t* b) {
    asm volatile(
        "mma.sync.aligned.m16n8k8.row.col.f32.tf32.tf32.f32 "
        "{%0,%1,%2,%3},{%4,%5,%6,%7},{%8,%9},{%0,%1,%2,%3};\n"
        : "+f"(c[0]), "+f"(c[1]), "+f"(c[2]), "+f"(c[3])
        : "r"(a[0]), "r"(a[1]), "r"(a[2]), "r"(a[3]), "r"(b[0]), "r"(b[1]));
}

__global__ __launch_bounds__(256, 2) void k_gemm() {
    __shared__ float As[2][GBK][SST];
    __shared__ float Bs[2][GBK][SST];

    int n_b = blockIdx.z;
    const float* A = g_xn + (size_t)n_b * C_DIM * P_DIM;
    const float* B = g_yn + (size_t)n_b * C_DIM * P_DIM;
    float* Cm      = g_cos + (size_t)n_b * P_DIM * P_DIM;

    int tid = threadIdx.x;
    int m0 = blockIdx.x * GBM, n0 = blockIdx.y * GBN;

    int lrow = tid >> 5;           // 0..7
    int lcol = (tid & 31) << 2;    // 0..124 step 4

    int warp = tid >> 5, lane = tid & 31;
    int wm = warp & 3, wn = warp >> 1 >> 1;  // wn = warp>>2
    int g = lane >> 2, t = lane & 3;

    float4 ra[2], rb[2];
    float acc[2][8][4] = {};

    const float* Ap0 = A + (size_t)lrow * P_DIM + m0 + lcol;
    const float* Bp0 = B + (size_t)lrow * P_DIM + n0 + lcol;

    // prefetch stage 0
    {
        ra[0] = *(const float4*)(Ap0);
        ra[1] = *(const float4*)(Ap0 + (size_t)8 * P_DIM);
        rb[0] = *(const float4*)(Bp0);
        rb[1] = *(const float4*)(Bp0 + (size_t)8 * P_DIM);
        *(float4*)&As[0][lrow    ][lcol] = ra[0];
        *(float4*)&As[0][lrow + 8][lcol] = ra[1];
        *(float4*)&Bs[0][lrow    ][lcol] = rb[0];
        *(float4*)&Bs[0][lrow + 8][lcol] = rb[1];
    }
    __syncthreads();

    int buf = 0;
    #pragma unroll 1
    for (int kt = 0; kt < C_DIM / GBK; kt++) {
        if (kt + 1 < C_DIM / GBK) {
            size_t koff = (size_t)(kt + 1) * GBK * P_DIM;
            ra[0] = *(const float4*)(Ap0 + koff);
            ra[1] = *(const float4*)(Ap0 + koff + (size_t)8 * P_DIM);
            rb[0] = *(const float4*)(Bp0 + koff);
            rb[1] = *(const float4*)(Bp0 + koff + (size_t)8 * P_DIM);
        }
        #pragma unroll
        for (int s = 0; s < 2; s++) {
            int ks = s * 8;
            uint32_t af[2][4], bfr[8][2];
            #pragma unroll
            for (int im = 0; im < 2; im++) {
                int mb = wm * 32 + im * 16;
                af[im][0] = __float_as_uint(As[buf][ks + t    ][mb + g    ]);
                af[im][1] = __float_as_uint(As[buf][ks + t    ][mb + g + 8]);
                af[im][2] = __float_as_uint(As[buf][ks + t + 4][mb + g    ]);
                af[im][3] = __float_as_uint(As[buf][ks + t + 4][mb + g + 8]);
            }
            #pragma unroll
            for (int jn = 0; jn < 8; jn++) {
                int nb = wn * 64 + jn * 8;
                bfr[jn][0] = __float_as_uint(Bs[buf][ks + t    ][nb + g]);
                bfr[jn][1] = __float_as_uint(Bs[buf][ks + t + 4][nb + g]);
            }
            #pragma unroll
            for (int im = 0; im < 2; im++)
                #pragma unroll
                for (int jn = 0; jn < 8; jn++)
                    mma_tf32(acc[im][jn], af[im], bfr[jn]);
        }
        if (kt + 1 < C_DIM / GBK) {
            *(float4*)&As[buf ^ 1][lrow    ][lcol] = ra[0];
            *(float4*)&As[buf ^ 1][lrow + 8][lcol] = ra[1];
            *(float4*)&Bs[buf ^ 1][lrow    ][lcol] = rb[0];
            *(float4*)&Bs[buf ^ 1][lrow + 8][lcol] = rb[1];
            __syncthreads();
            buf ^= 1;
        }
    }

    // epilogue
    #pragma unroll
    for (int im = 0; im < 2; im++) {
        #pragma unroll
        for (int jn = 0; jn < 8; jn++) {
            int m = m0 + wm * 32 + im * 16 + g;
            int n = n0 + wn * 64 + jn * 8 + t * 2;
            float2 v0 = make_float2(acc[im][jn][0], acc[im][jn][1]);
            float2 v1 = make_float2(acc[im][jn][2], acc[im][jn][3]);
            *(float2*)&Cm[(size_t)m * P_DIM + n]       = v0;
            *(float2*)&Cm[(size_t)(m + 8) * P_DIM + n] = v1;
        }
    }
}

// ---------------- K4: per-row max -> b2, bias --------------------------------
__global__ __launch_bounds__(256) void k_row() {
    int n = blockIdx.y;
    int p = blockIdx.x;
    const float4* row4 = (const float4*)(g_cos + ((size_t)n * P_DIM + p) * P_DIM);
    int tid = threadIdx.x;

    __shared__ float4 sr4[P_DIM / 4];   // 16 KB row cache
    __shared__ float red[256];

    float m = -1e30f;
    for (int i = tid; i < P_DIM / 4; i += 256) {
        float4 v = row4[i];
        sr4[i] = v;
        m = fmaxf(fmaxf(fmaxf(m, v.x), fmaxf(v.y, v.z)), v.w);
    }
    red[tid] = m; __syncthreads();
    for (int o = 128; o > 0; o >>= 1) {
        if (tid < o) red[tid] = fmaxf(red[tid], red[tid + o]);
        __syncthreads();
    }
    m = red[0];
    __syncthreads();

    float beta = 1.f / (HB * ((1.f - m) + EPS));
    float b2 = beta * LOG2E;

    float s = 0.f;
    for (int i = tid; i < P_DIM / 4; i += 256) {
        float4 v = sr4[i];
        s += exp2f(b2 * (v.x - m)) + exp2f(b2 * (v.y - m))
           + exp2f(b2 * (v.z - m)) + exp2f(b2 * (v.w - m));
    }
    red[tid] = s; __syncthreads();
    for (int o = 128; o > 0; o >>= 1) {
        if (tid < o) red[tid] += red[tid + o];
        __syncthreads();
    }
    if (tid == 0) {
        g_b2[n * P_DIM + p]   = b2;
        g_bias[n * P_DIM + p] = -b2 * m - log2f(red[0]);
    }
}

// ---------------- K5a: partial column max over p chunks ----------------------
__global__ __launch_bounds__(256) void k_colA() {
    int n  = blockIdx.z;
    int pc = blockIdx.y;
    int q  = blockIdx.x * 256 + threadIdx.x;
    const int PC = P_DIM / P_CHUNKS;   // 512
    int p0 = pc * PC;

    const float* cm = g_cos + (size_t)n * P_DIM * P_DIM + q;
    const float* b2 = g_b2   + n * P_DIM;
    const float* bi = g_bias + n * P_DIM;

    float M = 0.f;
    #pragma unroll 4
    for (int p = p0; p < p0 + PC; p++) {
        float c = cm[(size_t)p * P_DIM];
        M = fmaxf(M, exp2f(fmaf(b2[p], c, bi[p])));
    }
    g_colM[(n * P_CHUNKS + pc) * P_DIM + q] = M;
}

// ---------------- K5b: finish column max, sum over q -------------------------
__global__ __launch_bounds__(256) void k_colB() {
    int n = blockIdx.y;
    int q = blockIdx.x * 256 + threadIdx.x;
    float M = 0.f;
    #pragma unroll
    for (int pc = 0; pc < P_CHUNKS; pc++)
        M = fmaxf(M, g_colM[(n * P_CHUNKS + pc) * P_DIM + q]);

    __shared__ float red[256];
    red[threadIdx.x] = M; __syncthreads();
    for (int o = 128; o > 0; o >>= 1) {
        if (threadIdx.x < o) red[threadIdx.x] += red[threadIdx.x + o];
        __syncthreads();
    }
    if (threadIdx.x == 0)
        g_cxpart[n * 16 + blockIdx.x] = red[0];
}

// ---------------- K6: final scalar loss --------------------------------------
__global__ void k_final(float* __restrict__ out) {
    if (threadIdx.x == 0) {
        float loss = 0.f;
        for (int n = 0; n < N_BATCH; n++) {
            float s = 0.f;
            for (int b = 0; b < 16; b++) s += g_cxpart[n * 16 + b];
            float cx = s * (1.f / (float)P_DIM);
            loss += -logf(cx + EPS);
        }
        out[0] = loss * (1.f / (float)N_BATCH);
    }
}

// ---------------- launch ------------------------------------------------------
extern "C" void kernel_launch(void* const* d_in, const int* in_sizes, int n_in,
                              void* d_out, int out_size) {
    const float* x = (const float*)d_in[0];
    const float* y = (const float*)d_in[1];
    float* out = (float*)d_out;

    k_mean<<<C_DIM, 256>>>(y);
    k_norm<<<(N_BATCH * P_DIM) / 256, 256>>>(x, y);

    dim3 gg(P_DIM / GBM, P_DIM / GBN, N_BATCH);
    k_gemm<<<gg, 256>>>();

    dim3 gr(P_DIM, N_BATCH);
    k_row<<<gr, 256>>>();

    dim3 gca(P_DIM / 256, P_CHUNKS, N_BATCH);
    k_colA<<<gca, 256>>>();

    dim3 gcb(P_DIM / 256, N_BATCH);
    k_colB<<<gcb, 256>>>();

    k_final<<<1, 32>>>(out);
}

// round 4
// speedup vs baseline: 3.3611x; 1.8197x over previous
#include <cuda_runtime.h>
#include <cuda_fp16.h>
#include <math.h>
#include <stdint.h>

#define N_BATCH 4
#define C_DIM   256
#define P_DIM   4096
#define HB      0.5f
#define EPS     1e-5f
#define LOG2E   1.4426950408889634f

// ---------------- scratch ----------------------------------------------------
__device__ float  g_mu[C_DIM];
__device__ __half g_xh[(size_t)N_BATCH * C_DIM * P_DIM];   // [n][c][p] fp16 normalized
__device__ __half g_yh[(size_t)N_BATCH * C_DIM * P_DIM];
__device__ float  g_cos[(size_t)N_BATCH * P_DIM * P_DIM];  // 256 MB
__device__ float  g_b2[N_BATCH * P_DIM];
__device__ float  g_bias[N_BATCH * P_DIM];
#define P_CHUNKS 8
__device__ float  g_colM[N_BATCH * P_CHUNKS * P_DIM];
__device__ float  g_cxpart[N_BATCH * 16];

__device__ __forceinline__ uint32_t smem_u32(const void* p) {
    uint32_t a;
    asm("{ .reg .u64 t; cvta.to.shared.u64 t, %1; cvt.u32.u64 %0, t; }" : "=r"(a) : "l"(p));
    return a;
}

// ---------------- K1: per-channel mean of y ----------------------------------
__global__ void k_mean(const float* __restrict__ y) {
    int c = blockIdx.x;
    int tid = threadIdx.x;
    float s = 0.f;
    for (int n = 0; n < N_BATCH; n++) {
        const float* base = y + ((size_t)n * C_DIM + c) * P_DIM;
        for (int p = tid; p < P_DIM; p += 256) s += base[p];
    }
    __shared__ float sm[256];
    sm[tid] = s; __syncthreads();
    for (int o = 128; o > 0; o >>= 1) {
        if (tid < o) sm[tid] += sm[tid + o];
        __syncthreads();
    }
    if (tid == 0) g_mu[c] = sm[0] * (1.f / (float)(N_BATCH * P_DIM));
}

// ---------------- K2: center + normalize -> fp16 -----------------------------
__global__ __launch_bounds__(256) void k_norm(const float* __restrict__ x,
                                              const float* __restrict__ y) {
    __shared__ float mu[C_DIM];
    int tid = threadIdx.x;
    if (tid < C_DIM) mu[tid] = g_mu[tid];
    __syncthreads();

    int idx = blockIdx.x * 256 + tid;
    int n = idx / P_DIM, p = idx % P_DIM;
    const float* xb = x + (size_t)n * C_DIM * P_DIM + p;
    const float* yb = y + (size_t)n * C_DIM * P_DIM + p;

    float sx = 0.f, sy = 0.f;
    #pragma unroll 8
    for (int c = 0; c < C_DIM; c++) {
        float m  = mu[c];
        float xv = xb[(size_t)c * P_DIM] - m;
        float yv = yb[(size_t)c * P_DIM] - m;
        sx += xv * xv;
        sy += yv * yv;
    }
    float rx = rsqrtf(sx), ry = rsqrtf(sy);

    __half* xo = g_xh + (size_t)n * C_DIM * P_DIM + p;
    __half* yo = g_yh + (size_t)n * C_DIM * P_DIM + p;
    #pragma unroll 8
    for (int c = 0; c < C_DIM; c++) {
        float m = mu[c];
        xo[(size_t)c * P_DIM] = __float2half_rn((xb[(size_t)c * P_DIM] - m) * rx);
        yo[(size_t)c * P_DIM] = __float2half_rn((yb[(size_t)c * P_DIM] - m) * ry);
    }
}

// ---------------- K3: fp16 mma.sync GEMM  cos = A^T B ------------------------
// A = xh[n] (K x M, K-major), B = yh[n]. Block tile 128x128, BK=32.
// smem tiles: [k][m] halves, 128 halves (256B) per k-row, 16B-unit XOR swizzle.
// 8 warps: 4(m) x 2(n), warp tile 32x64, mma.m16n8k16 via ldmatrix.x4.trans.
#define BM 128
#define BN 128
#define BK 32
#define STAGE_BYTES 8192      // 32 * 128 * 2

__device__ __forceinline__ void mma_f16(float* c, const uint32_t* a, const uint32_t* b) {
    asm volatile(
        "mma.sync.aligned.m16n8k16.row.col.f32.f16.f16.f32 "
        "{%0,%1,%2,%3},{%4,%5,%6,%7},{%8,%9},{%0,%1,%2,%3};\n"
        : "+f"(c[0]), "+f"(c[1]), "+f"(c[2]), "+f"(c[3])
        : "r"(a[0]), "r"(a[1]), "r"(a[2]), "r"(a[3]), "r"(b[0]), "r"(b[1]));
}
__device__ __forceinline__ void ldsm4t(uint32_t* r, uint32_t addr) {
    asm volatile("ldmatrix.sync.aligned.m8n8.x4.trans.shared.b16 {%0,%1,%2,%3},[%4];"
                 : "=r"(r[0]), "=r"(r[1]), "=r"(r[2]), "=r"(r[3]) : "r"(addr));
}

__global__ __launch_bounds__(256, 2) void k_gemm_h() {
    __shared__ char sm[4 * STAGE_BYTES];    // A0 A1 B0 B1

    int nb = blockIdx.z;
    const __half* A = g_xh + (size_t)nb * C_DIM * P_DIM;
    const __half* B = g_yh + (size_t)nb * C_DIM * P_DIM;
    float* Cm       = g_cos + (size_t)nb * P_DIM * P_DIM;

    int tid = threadIdx.x;
    int m0 = blockIdx.x * BM, n0 = blockIdx.y * BN;
    int warp = tid >> 5, lane = tid & 31;
    int wm = warp & 3, wn = warp >> 2;
    int g = lane >> 2, t = lane & 3;
    int lg = lane >> 3, lr = lane & 7;

    uint32_t smA[2] = { smem_u32(sm),                smem_u32(sm) + STAGE_BYTES };
    uint32_t smB[2] = { smem_u32(sm) + 2*STAGE_BYTES, smem_u32(sm) + 3*STAGE_BYTES };

    // per-thread load mapping: 2 chunks of 16B for A, 2 for B per stage
    int lk[2], lj[2];
    #pragma unroll
    for (int v = 0; v < 2; v++) {
        int idx = v * 256 + tid;
        lk[v] = idx >> 4;          // k row 0..31
        lj[v] = idx & 15;          // 16B unit 0..15
    }

    uint4 ra[2], rb[2];
    float acc[2][8][4] = {};

    // prefetch stage 0
    #pragma unroll
    for (int v = 0; v < 2; v++) {
        ra[v] = *(const uint4*)(A + (size_t)lk[v] * P_DIM + m0 + lj[v] * 8);
        rb[v] = *(const uint4*)(B + (size_t)lk[v] * P_DIM + n0 + lj[v] * 8);
    }
    #pragma unroll
    for (int v = 0; v < 2; v++) {
        uint32_t off = lk[v] * 256 + ((lj[v] ^ (lk[v] & 7)) << 4);
        *(uint4*)(sm + (smA[0] - smem_u32(sm)) + off) = ra[v];
        *(uint4*)(sm + (smB[0] - smem_u32(sm)) + off) = rb[v];
    }
    __syncthreads();

    int buf = 0;
    const int NST = C_DIM / BK;    // 8
    #pragma unroll 1
    for (int st = 0; st < NST; st++) {
        if (st + 1 < NST) {
            size_t koff = (size_t)(st + 1) * BK * P_DIM;
            #pragma unroll
            for (int v = 0; v < 2; v++) {
                ra[v] = *(const uint4*)(A + koff + (size_t)lk[v] * P_DIM + m0 + lj[v] * 8);
                rb[v] = *(const uint4*)(B + koff + (size_t)lk[v] * P_DIM + n0 + lj[v] * 8);
            }
        }
        #pragma unroll
        for (int ks = 0; ks < BK; ks += 16) {
            uint32_t af[2][4], bf[8][2];
            // A fragments: two m16 tiles
            int ak = ks + lr + ((lg >> 1) << 3);
            #pragma unroll
            for (int im = 0; im < 2; im++) {
                int mj = ((wm * 32 + im * 16) >> 3) + (lg & 1);
                uint32_t addr = smA[buf] + ak * 256 + ((mj ^ (ak & 7)) << 4);
                ldsm4t(af[im], addr);
            }
            // B fragments: 8 n8 tiles via 4 x ldsm4t
            int bk = ks + lr + ((lg & 1) << 3);
            #pragma unroll
            for (int jp = 0; jp < 4; jp++) {
                int njc = ((wn * 64 + jp * 16) >> 3) + (lg >> 1);
                uint32_t addr = smB[buf] + bk * 256 + ((njc ^ (bk & 7)) << 4);
                uint32_t r[4];
                ldsm4t(r, addr);
                bf[jp * 2][0] = r[0]; bf[jp * 2][1] = r[1];
                bf[jp * 2 + 1][0] = r[2]; bf[jp * 2 + 1][1] = r[3];
            }
            #pragma unroll
            for (int im = 0; im < 2; im++)
                #pragma unroll
                for (int jn = 0; jn < 8; jn++)
                    mma_f16(acc[im][jn], af[im], bf[jn]);
        }
        if (st + 1 < NST) {
            __syncthreads();
            int nbuf = buf ^ 1;
            #pragma unroll
            for (int v = 0; v < 2; v++) {
                uint32_t off = lk[v] * 256 + ((lj[v] ^ (lk[v] & 7)) << 4);
                *(uint4*)(sm + (smA[nbuf] - smem_u32(sm)) + off) = ra[v];
                *(uint4*)(sm + (smB[nbuf] - smem_u32(sm)) + off) = rb[v];
            }
            __syncthreads();
            buf = nbuf;
        }
    }

    // epilogue: d0,d1 = (row g, col 2t..2t+1); d2,d3 = (row g+8)
    #pragma unroll
    for (int im = 0; im < 2; im++) {
        #pragma unroll
        for (int jn = 0; jn < 8; jn++) {
            int m = m0 + wm * 32 + im * 16 + g;
            int n = n0 + wn * 64 + jn * 8 + t * 2;
            *(float2*)&Cm[(size_t)m * P_DIM + n]       = make_float2(acc[im][jn][0], acc[im][jn][1]);
            *(float2*)&Cm[(size_t)(m + 8) * P_DIM + n] = make_float2(acc[im][jn][2], acc[im][jn][3]);
        }
    }
}

// ---------------- K4: per-row max -> b2, bias (row in registers) -------------
__global__ __launch_bounds__(256) void k_row() {
    int row = blockIdx.x;                       // 0 .. N*P-1
    int tid = threadIdx.x;
    const float4* r4 = (const float4*)(g_cos + (size_t)row * P_DIM);

    float4 v[4];
    #pragma unroll
    for (int i = 0; i < 4; i++) v[i] = r4[tid + i * 256];

    float m = -1e30f;
    #pragma unroll
    for (int i = 0; i < 4; i++)
        m = fmaxf(m, fmaxf(fmaxf(v[i].x, v[i].y), fmaxf(v[i].z, v[i].w)));

    __shared__ float red[256];
    red[tid] = m; __syncthreads();
    for (int o = 128; o > 0; o >>= 1) {
        if (tid < o) red[tid] = fmaxf(red[tid], red[tid + o]);
        __syncthreads();
    }
    m = red[0];
    __syncthreads();

    float beta = 1.f / (HB * ((1.f - m) + EPS));
    float b2 = beta * LOG2E;

    float s = 0.f;
    #pragma unroll
    for (int i = 0; i < 4; i++)
        s += exp2f(b2 * (v[i].x - m)) + exp2f(b2 * (v[i].y - m))
           + exp2f(b2 * (v[i].z - m)) + exp2f(b2 * (v[i].w - m));

    red[tid] = s; __syncthreads();
    for (int o = 128; o > 0; o >>= 1) {
        if (tid < o) red[tid] += red[tid + o];
        __syncthreads();
    }
    if (tid == 0) {
        g_b2[row]   = b2;
        g_bias[row] = -b2 * m - log2f(red[0]);
    }
}

// ---------------- K5a: partial column max ------------------------------------
__global__ __launch_bounds__(256) void k_colA() {
    int n  = blockIdx.z;
    int pc = blockIdx.y;
    int q  = blockIdx.x * 256 + threadIdx.x;
    const int PC = P_DIM / P_CHUNKS;
    int p0 = pc * PC;

    const float* cm = g_cos + (size_t)n * P_DIM * P_DIM + q;
    const float* b2 = g_b2   + n * P_DIM;
    const float* bi = g_bias + n * P_DIM;

    float M = 0.f;
    #pragma unroll 4
    for (int p = p0; p < p0 + PC; p++) {
        float c = cm[(size_t)p * P_DIM];
        M = fmaxf(M, exp2f(fmaf(b2[p], c, bi[p])));
    }
    g_colM[(n * P_CHUNKS + pc) * P_DIM + q] = M;
}

// ---------------- K5b: finish column max, sum over q -------------------------
__global__ __launch_bounds__(256) void k_colB() {
    int n = blockIdx.y;
    int q = blockIdx.x * 256 + threadIdx.x;
    float M = 0.f;
    #pragma unroll
    for (int pc = 0; pc < P_CHUNKS; pc++)
        M = fmaxf(M, g_colM[(n * P_CHUNKS + pc) * P_DIM + q]);

    __shared__ float red[256];
    red[threadIdx.x] = M; __syncthreads();
    for (int o = 128; o > 0; o >>= 1) {
        if (threadIdx.x < o) red[threadIdx.x] += red[threadIdx.x + o];
        __syncthreads();
    }
    if (threadIdx.x == 0)
        g_cxpart[n * 16 + blockIdx.x] = red[0];
}

// ---------------- K6: final scalar loss --------------------------------------
__global__ void k_final(float* __restrict__ out) {
    if (threadIdx.x == 0) {
        float loss = 0.f;
        for (int n = 0; n < N_BATCH; n++) {
            float s = 0.f;
            for (int b = 0; b < 16; b++) s += g_cxpart[n * 16 + b];
            float cx = s * (1.f / (float)P_DIM);
            loss += -logf(cx + EPS);
        }
        out[0] = loss * (1.f / (float)N_BATCH);
    }
}

// ---------------- launch ------------------------------------------------------
extern "C" void kernel_launch(void* const* d_in, const int* in_sizes, int n_in,
                              void* d_out, int out_size) {
    const float* x = (const float*)d_in[0];
    const float* y = (const float*)d_in[1];
    float* out = (float*)d_out;

    k_mean<<<C_DIM, 256>>>(y);
    k_norm<<<(N_BATCH * P_DIM) / 256, 256>>>(x, y);

    dim3 gg(P_DIM / BM, P_DIM / BN, N_BATCH);
    k_gemm_h<<<gg, 256>>>();

    k_row<<<N_BATCH * P_DIM, 256>>>();

    dim3 gca(P_DIM / 256, P_CHUNKS, N_BATCH);
    k_colA<<<gca, 256>>>();

    dim3 gcb(P_DIM / 256, N_BATCH);
    k_colB<<<gcb, 256>>>();

    k_final<<<1, 32>>>(out);
}